// round 5
// baseline (speedup 1.0000x reference)
#include <cuda_runtime.h>
#include <cuda_bf16.h>
#include <math.h>

#define CN 128
#define SS 56
#define KK 3
#define NTAP 36
#define PROWS 61          // padded rows: y in [-2, 58]
#define PITCH 65          // padded col pitch (kills bank conflicts)
#define USPLIT 4
#define UCH (CN / USPLIT) // 32 u-values per block
#define NT 448            // 56 rows x 8 col-groups of 7

// MUFU intrinsics via PTX (guaranteed regardless of fast-math flags)
__device__ __forceinline__ float fast_lg2(float v) {
    float r;
    asm("lg2.approx.f32 %0, %1;" : "=f"(r) : "f"(v));
    return r;
}
__device__ __forceinline__ float fast_ex2(float v) {
    float r;
    asm("ex2.approx.f32 %0, %1;" : "=f"(r) : "f"(v));
    return r;
}

// scratch (allocation-free rule: __device__ globals)
__device__ float d_bank[CN * CN * NTAP];   // g[i][u][t]
__device__ float d_biasn[CN];              // bias^nU
__device__ float d_partial[USPLIT][2 * CN * SS * SS];

// ---------------------------------------------------------------------------
// Kernel 1: precompute gaussian bank + bias^nU
// grid: (CN) blocks of CN threads; block = i, thread = u
// ---------------------------------------------------------------------------
__global__ void bank_kernel(const float* __restrict__ theta,
                            const float* __restrict__ p,
                            const float* __restrict__ sig,
                            const float* __restrict__ a,
                            const float* __restrict__ bias,
                            const float* __restrict__ nU) {
    int i = blockIdx.x;
    int u = threadIdx.x;
    int iu = i * CN + u;
    float th = theta[iu];
    float pv = p[iu];
    float sg = sig[iu];
    float av = a[iu];
    float st, ct;
    sincosf(th, &st, &ct);   // theta up to ~300 rad -> precise path required
    float amp = av / (2.0f * 3.14159265358979323846f * pv * sg);
    float ip2 = 1.0f / (pv * pv);
    float is2 = 1.0f / (sg * sg);
    float* out = &d_bank[iu * NTAP];
    // coords = linspace(-3, 3, 6) = -3 + 1.2*k
    #pragma unroll
    for (int r = 0; r < 6; r++) {
        float xv = -3.0f + 1.2f * (float)r;
        #pragma unroll
        for (int c = 0; c < 6; c++) {
            float yv = -3.0f + 1.2f * (float)c;
            float xr = xv * ct + yv * st;
            float yr = -xv * st + yv * ct;
            out[r * 6 + c] = amp * expf(-0.5f * (xr * xr * ip2 + yr * yr * is2));
        }
    }
    if (u == 0) d_biasn[i] = powf(bias[i], nU[i]);
}

// ---------------------------------------------------------------------------
// Kernel 2: main — per (b,i, u-chunk): denom partial sums
// grid: (B*CN, USPLIT); block: 448 threads = 56 rows x 8 strips of 7 cols
// ---------------------------------------------------------------------------
__global__ __launch_bounds__(NT) void main_kernel(const float* __restrict__ x,
                                                  const float* __restrict__ nI) {
    __shared__ float sL[PROWS * PITCH];   // log2(x), pad = -1e30 (-> exp2 = 0)
    __shared__ float sP[PROWS * PITCH];   // x^n, pad = 0 (constant across u)
    __shared__ float sG[UCH * NTAP];
    __shared__ float sN[UCH];

    const int bi = blockIdx.x;          // b*CN + i
    const int uc = blockIdx.y;          // u chunk
    const int i  = bi & (CN - 1);
    const int tid = threadIdx.x;

    // init padded buffers
    for (int idx = tid; idx < PROWS * PITCH; idx += NT) {
        sL[idx] = -1e30f;
        sP[idx] = 0.0f;
    }
    __syncthreads();
    // interior: log2(x)  (log computed ONCE; every pow becomes exp2(n*L))
    const float* xr = x + bi * (SS * SS);
    for (int idx = tid; idx < SS * SS; idx += NT) {
        int y = idx / SS;
        int xx = idx - y * SS;
        sL[(y + 2) * PITCH + xx + 2] = fast_lg2(xr[idx]);
    }
    // gaussian rows + exponents for this u-chunk
    const float* gb = d_bank + (i * CN + uc * UCH) * NTAP;
    for (int idx = tid; idx < UCH * NTAP; idx += NT) sG[idx] = gb[idx];
    if (tid < UCH) sN[tid] = nI[i * CN + uc * UCH + tid];

    // per-thread interior smem offsets for the pow phase (loop-invariant)
    int offs[7];
    #pragma unroll
    for (int k = 0; k < 7; k++) {
        int idx = tid + k * NT;          // 7*448 = 3136 exactly
        int y = idx / SS;
        int xx = idx - y * SS;
        offs[k] = (y + 2) * PITCH + xx + 2;
    }

    const int row = tid >> 3;            // 0..55
    const int x0 = (tid & 7) * 7;        // strip start col

    float acc[7];
    #pragma unroll
    for (int o = 0; o < 7; o++) acc[o] = 0.0f;

    for (int uu = 0; uu < UCH; uu++) {
        __syncthreads();                 // prev conv reads done before P rewrite
        float n = sN[uu];
        #pragma unroll
        for (int k = 0; k < 7; k++)
            sP[offs[k]] = fast_ex2(n * sL[offs[k]]);
        __syncthreads();

        const float* gr = &sG[uu * NTAP];
        #pragma unroll
        for (int ky = 0; ky < 6; ky++) {
            // tap row for output row `row`, kernel row ky: padded row = row+ky
            const float* pr = &sP[(row + ky) * PITCH + x0];
            float w[12];                 // sliding window: 12 cols -> 7 outputs
            #pragma unroll
            for (int j = 0; j < 12; j++) w[j] = pr[j];
            #pragma unroll
            for (int kx = 0; kx < 6; kx++) {
                float gv = gr[ky * 6 + kx];
                #pragma unroll
                for (int o = 0; o < 7; o++)
                    acc[o] += w[o + kx] * gv;
            }
        }
    }

    float* out = &d_partial[uc][bi * (SS * SS) + row * SS + x0];
    #pragma unroll
    for (int o = 0; o < 7; o++) out[o] = acc[o];
}

// ---------------------------------------------------------------------------
// Kernel 3: combine — out = x^nU / (bias^nU + sum of partials)
// ---------------------------------------------------------------------------
__global__ void combine_kernel(const float* __restrict__ x,
                               const float* __restrict__ nU,
                               float* __restrict__ out, int total) {
    int idx = blockIdx.x * blockDim.x + threadIdx.x;
    if (idx >= total) return;
    int i = (idx / (SS * SS)) & (CN - 1);
    float d = d_biasn[i] + d_partial[0][idx] + d_partial[1][idx]
                         + d_partial[2][idx] + d_partial[3][idx];
    float num = fast_ex2(nU[i] * fast_lg2(x[idx]));
    out[idx] = num / d;
}

// ---------------------------------------------------------------------------
extern "C" void kernel_launch(void* const* d_in, const int* in_sizes, int n_in,
                              void* d_out, int out_size) {
    const float* x     = (const float*)d_in[0];
    const float* theta = (const float*)d_in[1];
    const float* p     = (const float*)d_in[2];
    const float* sig   = (const float*)d_in[3];
    const float* a     = (const float*)d_in[4];
    const float* nI    = (const float*)d_in[5];
    const float* nU    = (const float*)d_in[6];
    const float* bias  = (const float*)d_in[7];
    float* out = (float*)d_out;

    int B = in_sizes[0] / (CN * SS * SS);   // = 2

    bank_kernel<<<CN, CN>>>(theta, p, sig, a, bias, nU);
    main_kernel<<<dim3(B * CN, USPLIT), NT>>>(x, nI);
    combine_kernel<<<(out_size + 255) / 256, 256>>>(x, nU, out, out_size);
}

// round 7
// speedup vs baseline: 1.0622x; 1.0622x over previous
#include <cuda_runtime.h>
#include <cuda_bf16.h>
#include <math.h>

#define CN 128
#define SS 56
#define NTAP 36
#define PROWS 61          // padded rows: y in [-2, 58]
#define PITCH 65          // padded col pitch
#define USPLIT 4
#define UCH (CN / USPLIT) // 32 u-values per block -> 16 u-pairs
#define NPAIR (UCH / 2)
#define NT 448            // 56 rows x 8 strips of 7 cols

// ---------------------------------------------------------------------------
// intrinsics
// ---------------------------------------------------------------------------
__device__ __forceinline__ float fast_lg2(float v) {
    float r; asm("lg2.approx.f32 %0, %1;" : "=f"(r) : "f"(v)); return r;
}
__device__ __forceinline__ float fast_ex2(float v) {
    float r; asm("ex2.approx.f32 %0, %1;" : "=f"(r) : "f"(v)); return r;
}
__device__ __forceinline__ unsigned long long lds64(unsigned addr) {
    unsigned long long r;
    asm volatile("ld.shared.b64 %0, [%1];" : "=l"(r) : "r"(addr));
    return r;
}
__device__ __forceinline__ void sts64(unsigned addr, unsigned long long v) {
    asm volatile("st.shared.b64 [%0], %1;" :: "r"(addr), "l"(v) : "memory");
}
// packed dual-FMA: d.lo += a.lo*b.lo ; d.hi += a.hi*b.hi   (FFMA2 on sm_103a)
__device__ __forceinline__ void fma2(unsigned long long& d,
                                     unsigned long long a,
                                     unsigned long long b) {
    asm("fma.rn.f32x2 %0, %1, %2, %0;" : "+l"(d) : "l"(a), "l"(b));
}
__device__ __forceinline__ unsigned long long pack2(float lo, float hi) {
    unsigned long long r;
    asm("mov.b64 %0, {%1, %2};" : "=l"(r) : "f"(lo), "f"(hi));
    return r;
}
__device__ __forceinline__ float2 unpack2(unsigned long long v) {
    float2 r;
    asm("mov.b64 {%0, %1}, %2;" : "=f"(r.x), "=f"(r.y) : "l"(v));
    return r;
}

// scratch (allocation-free rule: __device__ globals)
__device__ float d_bank[CN * CN * NTAP];   // g[i][u][t]
__device__ float d_biasn[CN];              // bias^nU
__device__ float d_partial[USPLIT][2 * CN * SS * SS];

// ---------------------------------------------------------------------------
// Kernel 1: precompute gaussian bank + bias^nU
// ---------------------------------------------------------------------------
__global__ void bank_kernel(const float* __restrict__ theta,
                            const float* __restrict__ p,
                            const float* __restrict__ sig,
                            const float* __restrict__ a,
                            const float* __restrict__ bias,
                            const float* __restrict__ nU) {
    int i = blockIdx.x;
    int u = threadIdx.x;
    int iu = i * CN + u;
    float th = theta[iu];
    float pv = p[iu];
    float sg = sig[iu];
    float av = a[iu];
    float st, ct;
    sincosf(th, &st, &ct);   // theta up to ~300 rad -> precise path required
    float amp = av / (2.0f * 3.14159265358979323846f * pv * sg);
    float ip2 = 1.0f / (pv * pv);
    float is2 = 1.0f / (sg * sg);
    float* out = &d_bank[iu * NTAP];
    #pragma unroll
    for (int r = 0; r < 6; r++) {
        float xv = -3.0f + 1.2f * (float)r;
        #pragma unroll
        for (int c = 0; c < 6; c++) {
            float yv = -3.0f + 1.2f * (float)c;
            float xr = xv * ct + yv * st;
            float yr = -xv * st + yv * ct;
            out[r * 6 + c] = amp * expf(-0.5f * (xr * xr * ip2 + yr * yr * is2));
        }
    }
    if (u == 0) d_biasn[i] = powf(bias[i], nU[i]);
}

// ---------------------------------------------------------------------------
// Kernel 2: main — u-pair packed FFMA2 conv
// grid: (B*CN, USPLIT); block: 448 threads = 56 rows x 8 strips of 7 cols
// ---------------------------------------------------------------------------
__global__ __launch_bounds__(NT) void main_kernel(const float* __restrict__ x,
                                                  const float* __restrict__ nI) {
    // interleaved pair plane: (P_u, P_{u+1}) at element idx -> floats [2*idx, 2*idx+1]
    __shared__ float sP2[PROWS * PITCH * 2];
    __shared__ float sG2[NPAIR * NTAP * 2];  // (g_u[t], g_{u+1}[t]) interleaved
    __shared__ float sN[UCH];

    const int bi = blockIdx.x;          // b*CN + i
    const int uc = blockIdx.y;          // u chunk
    const int i  = bi & (CN - 1);
    const int tid = threadIdx.x;

    unsigned sp2_base, sg2_base;
    {
        sp2_base = (unsigned)__cvta_generic_to_shared(sP2);
        sg2_base = (unsigned)__cvta_generic_to_shared(sG2);
    }

    // zero the pair plane (pads stay 0 forever; interior rewritten each pair)
    for (int idx = tid; idx < PROWS * PITCH * 2; idx += NT) sP2[idx] = 0.0f;

    // gaussian weights for this u-chunk, interleaved by pair
    const float* gb = d_bank + (i * CN + uc * UCH) * NTAP;
    for (int idx = tid; idx < UCH * NTAP; idx += NT) {
        int u = idx / NTAP;
        int t = idx - u * NTAP;
        sG2[(u >> 1) * (NTAP * 2) + t * 2 + (u & 1)] = gb[idx];
    }
    if (tid < UCH) sN[tid] = nI[i * CN + uc * UCH + tid];

    // per-thread log2(x) at its 7 pow positions, kept in registers
    const float* xr = x + bi * (SS * SS);
    float Lr[7];
    int offs[7];                         // element offsets in padded plane
    #pragma unroll
    for (int k = 0; k < 7; k++) {
        int idx = tid + k * NT;          // 7*448 = 3136 exactly
        int y = idx / SS;
        int xx = idx - y * SS;
        offs[k] = (y + 2) * PITCH + xx + 2;
        Lr[k] = fast_lg2(xr[idx]);
    }

    const int row = tid >> 3;            // 0..55
    const int x0 = (tid & 7) * 7;        // strip start col

    unsigned long long acc[7];
    #pragma unroll
    for (int o = 0; o < 7; o++) acc[o] = 0ull;

    for (int pp = 0; pp < NPAIR; pp++) {
        __syncthreads();                 // prev conv reads done before rewrite
        float n0 = sN[2 * pp];
        float n1 = sN[2 * pp + 1];
        #pragma unroll
        for (int k = 0; k < 7; k++) {
            float p0 = fast_ex2(n0 * Lr[k]);
            float p1 = fast_ex2(n1 * Lr[k]);
            sts64(sp2_base + 8u * (unsigned)offs[k], pack2(p0, p1));
        }
        __syncthreads();

        unsigned gwb = sg2_base + (unsigned)(pp * NTAP * 2) * 4u;
        #pragma unroll
        for (int ky = 0; ky < 6; ky++) {
            unsigned wb = sp2_base + 8u * (unsigned)((row + ky) * PITCH + x0);
            unsigned long long w[12];    // sliding window pairs
            #pragma unroll
            for (int j = 0; j < 12; j++) w[j] = lds64(wb + 8u * j);
            #pragma unroll
            for (int kx = 0; kx < 6; kx++) {
                unsigned long long gv = lds64(gwb + 8u * (ky * 6 + kx));
                #pragma unroll
                for (int o = 0; o < 7; o++)
                    fma2(acc[o], w[o + kx], gv);
            }
        }
    }

    float* out = &d_partial[uc][bi * (SS * SS) + row * SS + x0];
    #pragma unroll
    for (int o = 0; o < 7; o++) {
        float2 v = unpack2(acc[o]);
        out[o] = v.x + v.y;
    }
}

// ---------------------------------------------------------------------------
// Kernel 3: combine — out = x^nU / (bias^nU + sum of partials)
// ---------------------------------------------------------------------------
__global__ void combine_kernel(const float* __restrict__ x,
                               const float* __restrict__ nU,
                               float* __restrict__ out, int total) {
    int idx = blockIdx.x * blockDim.x + threadIdx.x;
    if (idx >= total) return;
    int i = (idx / (SS * SS)) & (CN - 1);
    float d = d_biasn[i] + d_partial[0][idx] + d_partial[1][idx]
                         + d_partial[2][idx] + d_partial[3][idx];
    float num = fast_ex2(nU[i] * fast_lg2(x[idx]));
    out[idx] = num / d;
}

// ---------------------------------------------------------------------------
extern "C" void kernel_launch(void* const* d_in, const int* in_sizes, int n_in,
                              void* d_out, int out_size) {
    const float* x     = (const float*)d_in[0];
    const float* theta = (const float*)d_in[1];
    const float* p     = (const float*)d_in[2];
    const float* sig   = (const float*)d_in[3];
    const float* a     = (const float*)d_in[4];
    const float* nI    = (const float*)d_in[5];
    const float* nU    = (const float*)d_in[6];
    const float* bias  = (const float*)d_in[7];
    float* out = (float*)d_out;

    int B = in_sizes[0] / (CN * SS * SS);   // = 2

    bank_kernel<<<CN, CN>>>(theta, p, sig, a, bias, nU);
    main_kernel<<<dim3(B * CN, USPLIT), NT>>>(x, nI);
    combine_kernel<<<(out_size + 255) / 256, 256>>>(x, nU, out, out_size);
}

// round 10
// speedup vs baseline: 1.5393x; 1.4491x over previous
#include <cuda_runtime.h>
#include <cuda_bf16.h>
#include <math.h>

#define CN 128
#define SS 56
#define NTAP 36
#define PROWS 61          // padded rows: y in [-2, 58]
#define PITCH 65          // padded col pitch
#define USPLIT 8
#define UCH (CN / USPLIT) // 16 u-values per block -> 8 pairs
#define NPAIR (UCH / 2)
#define NT 224            // 28 row-pairs x 8 strips of 7 cols

// ---------------------------------------------------------------------------
// intrinsics
// ---------------------------------------------------------------------------
__device__ __forceinline__ float fast_lg2(float v) {
    float r; asm("lg2.approx.f32 %0, %1;" : "=f"(r) : "f"(v)); return r;
}
__device__ __forceinline__ float fast_ex2(float v) {
    float r; asm("ex2.approx.f32 %0, %1;" : "=f"(r) : "f"(v)); return r;
}
__device__ __forceinline__ unsigned long long lds64(unsigned addr) {
    unsigned long long r;
    asm volatile("ld.shared.b64 %0, [%1];" : "=l"(r) : "r"(addr));
    return r;
}
__device__ __forceinline__ void sts64(unsigned addr, unsigned long long v) {
    asm volatile("st.shared.b64 [%0], %1;" :: "r"(addr), "l"(v) : "memory");
}
// packed dual-FMA: d.lo += a.lo*b.lo ; d.hi += a.hi*b.hi
__device__ __forceinline__ void fma2(unsigned long long& d,
                                     unsigned long long a,
                                     unsigned long long b) {
    asm("fma.rn.f32x2 %0, %1, %2, %0;" : "+l"(d) : "l"(a), "l"(b));
}
__device__ __forceinline__ unsigned long long pack2(float lo, float hi) {
    unsigned long long r;
    asm("mov.b64 %0, {%1, %2};" : "=l"(r) : "f"(lo), "f"(hi));
    return r;
}
__device__ __forceinline__ float2 unpack2(unsigned long long v) {
    float2 r;
    asm("mov.b64 {%0, %1}, %2;" : "=f"(r.x), "=f"(r.y) : "l"(v));
    return r;
}

// scratch (allocation-free rule: __device__ globals)
__device__ float d_bank[CN * CN * NTAP];   // g[i][u][t]
__device__ float d_biasn[CN];              // bias^nU
__device__ float d_partial[USPLIT][2 * CN * SS * SS];

// ---------------------------------------------------------------------------
// Kernel 1: precompute gaussian bank + bias^nU
// ---------------------------------------------------------------------------
__global__ void bank_kernel(const float* __restrict__ theta,
                            const float* __restrict__ p,
                            const float* __restrict__ sig,
                            const float* __restrict__ a,
                            const float* __restrict__ bias,
                            const float* __restrict__ nU) {
    int i = blockIdx.x;
    int u = threadIdx.x;
    int iu = i * CN + u;
    float th = theta[iu];
    float pv = p[iu];
    float sg = sig[iu];
    float av = a[iu];
    float st, ct;
    sincosf(th, &st, &ct);   // theta up to ~300 rad -> precise path required
    float amp = av / (2.0f * 3.14159265358979323846f * pv * sg);
    float ip2 = 1.0f / (pv * pv);
    float is2 = 1.0f / (sg * sg);
    float* out = &d_bank[iu * NTAP];
    #pragma unroll
    for (int r = 0; r < 6; r++) {
        float xv = -3.0f + 1.2f * (float)r;
        #pragma unroll
        for (int c = 0; c < 6; c++) {
            float yv = -3.0f + 1.2f * (float)c;
            float xr = xv * ct + yv * st;
            float yr = -xv * st + yv * ct;
            out[r * 6 + c] = amp * expf(-0.5f * (xr * xr * ip2 + yr * yr * is2));
        }
    }
    if (u == 0) d_biasn[i] = powf(bias[i], nU[i]);
}

// ---------------------------------------------------------------------------
// Kernel 2: main — u-pair packed FFMA2 conv, 2x7 output tile per thread
// grid: (B*CN, USPLIT); block: 224 threads = 28 row-pairs x 8 strips
// ---------------------------------------------------------------------------
__global__ __launch_bounds__(NT) void main_kernel(const float* __restrict__ x,
                                                  const float* __restrict__ nI) {
    // interleaved pair plane: (P_u, P_{u+1}) at element idx
    __shared__ float sP2[PROWS * PITCH * 2];
    __shared__ float sG2[NPAIR * NTAP * 2];  // (g_u[t], g_{u+1}[t]) interleaved
    __shared__ float sN[UCH];

    const int bi = blockIdx.x;          // b*CN + i
    const int uc = blockIdx.y;          // u chunk
    const int i  = bi & (CN - 1);
    const int tid = threadIdx.x;

    const unsigned sp2_base = (unsigned)__cvta_generic_to_shared(sP2);
    const unsigned sg2_base = (unsigned)__cvta_generic_to_shared(sG2);

    // zero the pair plane (pads stay 0 forever; interior rewritten each pair)
    for (int idx = tid; idx < PROWS * PITCH * 2; idx += NT) sP2[idx] = 0.0f;

    // gaussian weights for this u-chunk, interleaved by pair
    const float* gb = d_bank + (i * CN + uc * UCH) * NTAP;
    for (int idx = tid; idx < UCH * NTAP; idx += NT) {
        int u = idx / NTAP;
        int t = idx - u * NTAP;
        sG2[(u >> 1) * (NTAP * 2) + t * 2 + (u & 1)] = gb[idx];
    }
    if (tid < UCH) sN[tid] = nI[i * CN + uc * UCH + tid];

    const int rp    = tid >> 3;          // 0..27  -> out rows 2rp, 2rp+1
    const int strip = tid & 7;           // 0..7   -> out cols strip*7 ..+6
    const int r0 = 2 * rp;
    const int x0 = strip * 7;

    // per-thread log2(x) over its own 2x7 tile, kept in registers
    const float* xr = x + bi * (SS * SS);
    float Lr[14];
    #pragma unroll
    for (int rr = 0; rr < 2; rr++)
        #pragma unroll
        for (int c = 0; c < 7; c++)
            Lr[rr * 7 + c] = fast_lg2(xr[(r0 + rr) * SS + x0 + c]);

    // smem byte bases (immediate offsets elsewhere)
    const unsigned powbase  = sp2_base + 8u * (unsigned)((r0 + 2) * PITCH + x0 + 2);
    const unsigned convbase = sp2_base + 8u * (unsigned)(r0 * PITCH + x0);

    unsigned long long accA[7], accB[7];
    #pragma unroll
    for (int o = 0; o < 7; o++) { accA[o] = 0ull; accB[o] = 0ull; }

    for (int pp = 0; pp < NPAIR; pp++) {
        __syncthreads();                 // prev conv reads done before rewrite
        float n0 = sN[2 * pp];
        float n1 = sN[2 * pp + 1];
        #pragma unroll
        for (int rr = 0; rr < 2; rr++)
            #pragma unroll
            for (int c = 0; c < 7; c++) {
                float L = Lr[rr * 7 + c];
                sts64(powbase + (unsigned)(rr * PITCH + c) * 8u,
                      pack2(fast_ex2(n0 * L), fast_ex2(n1 * L)));
            }
        __syncthreads();

        const unsigned gwb = sg2_base + (unsigned)(pp * NTAP * 2) * 4u;
        #pragma unroll
        for (int ir = 0; ir < 7; ir++) {   // input padded rows r0 .. r0+6
            unsigned wb = convbase + (unsigned)(ir * PITCH) * 8u;
            unsigned long long w[12];      // sliding window pairs
            #pragma unroll
            for (int j = 0; j < 12; j++) w[j] = lds64(wb + 8u * j);
            if (ir < 6) {                  // out row r0, kernel row ir
                #pragma unroll
                for (int kx = 0; kx < 6; kx++) {
                    unsigned long long gv = lds64(gwb + 8u * (ir * 6 + kx));
                    #pragma unroll
                    for (int o = 0; o < 7; o++) fma2(accA[o], w[o + kx], gv);
                }
            }
            if (ir >= 1) {                 // out row r0+1, kernel row ir-1
                #pragma unroll
                for (int kx = 0; kx < 6; kx++) {
                    unsigned long long gv = lds64(gwb + 8u * ((ir - 1) * 6 + kx));
                    #pragma unroll
                    for (int o = 0; o < 7; o++) fma2(accB[o], w[o + kx], gv);
                }
            }
        }
    }

    float* outp = &d_partial[uc][bi * (SS * SS) + r0 * SS + x0];
    #pragma unroll
    for (int o = 0; o < 7; o++) {
        float2 va = unpack2(accA[o]);
        float2 vb = unpack2(accB[o]);
        outp[o]      = va.x + va.y;
        outp[SS + o] = vb.x + vb.y;
    }
}

// ---------------------------------------------------------------------------
// Kernel 3: combine — out = x^nU / (bias^nU + sum of partials)
// ---------------------------------------------------------------------------
__global__ void combine_kernel(const float* __restrict__ x,
                               const float* __restrict__ nU,
                               float* __restrict__ out, int total) {
    int idx = blockIdx.x * blockDim.x + threadIdx.x;
    if (idx >= total) return;
    int i = (idx / (SS * SS)) & (CN - 1);
    float d = d_biasn[i];
    #pragma unroll
    for (int s = 0; s < USPLIT; s++) d += d_partial[s][idx];
    float num = fast_ex2(nU[i] * fast_lg2(x[idx]));
    out[idx] = num / d;
}

// ---------------------------------------------------------------------------
extern "C" void kernel_launch(void* const* d_in, const int* in_sizes, int n_in,
                              void* d_out, int out_size) {
    const float* x     = (const float*)d_in[0];
    const float* theta = (const float*)d_in[1];
    const float* p     = (const float*)d_in[2];
    const float* sig   = (const float*)d_in[3];
    const float* a     = (const float*)d_in[4];
    const float* nI    = (const float*)d_in[5];
    const float* nU    = (const float*)d_in[6];
    const float* bias  = (const float*)d_in[7];
    float* out = (float*)d_out;

    int B = in_sizes[0] / (CN * SS * SS);   // = 2

    bank_kernel<<<CN, CN>>>(theta, p, sig, a, bias, nU);
    main_kernel<<<dim3(B * CN, USPLIT), NT>>>(x, nI);
    combine_kernel<<<(out_size + 255) / 256, 256>>>(x, nU, out, out_size);
}